// round 2
// baseline (speedup 1.0000x reference)
#include <cuda_runtime.h>

// ---------------------------------------------------------------------------
// PointNet++ SetAbstraction x4, B=16, N=4096
// ---------------------------------------------------------------------------

#define NBATCH 16
#define NPTS0  4096

// ---------------- device scratch (no allocations allowed) ------------------
__device__ float g_xyz0[NBATCH * NPTS0 * 3];
__device__ float g_pts0[NBATCH * NPTS0 * 9];
__device__ float g_nx1[NBATCH * 1024 * 3];
__device__ float g_f1 [NBATCH * 1024 * 64];
__device__ float g_nx2[NBATCH * 256 * 3];
__device__ float g_f2 [NBATCH * 256 * 128];
__device__ float g_nx3[NBATCH * 64 * 3];
__device__ float g_f3 [NBATCH * 64 * 256];
__device__ float g_nx4[NBATCH * 16 * 3];
__device__ float g_f4 [NBATCH * 16 * 512];

// ---------------- d_out offsets (float elements) ----------------------------
// order: l_xyz[0..4] transposed, then l_pts[1..4] transposed
#define O1 0        // [16,3,4096]
#define O2 196608   // [16,3,1024]
#define O3 245760   // [16,3,256]
#define O4 258048   // [16,3,64]
#define O5 261120   // [16,3,16]
#define O6 261888   // [16,64,1024]
#define O7 1310464  // [16,128,256]
#define O8 1834752  // [16,256,64]
#define O9 2096896  // [16,512,16]

// non-fma sum of three squares (mimic XLA elementwise square + sequential sum)
__device__ __forceinline__ float sq3(float a, float b, float c) {
    return __fadd_rn(__fadd_rn(__fmul_rn(a, a), __fmul_rn(b, b)), __fmul_rn(c, c));
}

// ---------------------------------------------------------------------------
// Transpose [B,9,N] -> point-major scratch; also emits output region 1.
// ---------------------------------------------------------------------------
__global__ void k_transpose(const float* __restrict__ in, float* __restrict__ out1) {
    int i = blockIdx.x * blockDim.x + threadIdx.x;
    if (i >= NBATCH * NPTS0) return;
    int b = i >> 12;
    int n = i & (NPTS0 - 1);
    const float* src = in + (size_t)b * 9 * NPTS0;
    float v[9];
#pragma unroll
    for (int c = 0; c < 9; c++) v[c] = src[c * NPTS0 + n];
#pragma unroll
    for (int c = 0; c < 9; c++) g_pts0[(size_t)i * 9 + c] = v[c];
#pragma unroll
    for (int c = 0; c < 3; c++) g_xyz0[(size_t)i * 3 + c] = v[c];
#pragma unroll
    for (int c = 0; c < 3; c++) out1[((size_t)b * 3 + c) * NPTS0 + n] = v[c];
}

// ---------------------------------------------------------------------------
// Farthest point sampling: one block per batch. Coords + running min-dist live
// in registers (PPT points per thread). Per iteration: broadcast far coords,
// update dists, block argmax (tie-break: smallest index == jnp.argmax).
// Writes new_xyz point-major AND transposed into d_out.
// ---------------------------------------------------------------------------
template <int NP, int S, int T>
__global__ __launch_bounds__(T) void k_fps(const float* __restrict__ xyz,
                                           float* __restrict__ nx,
                                           float* __restrict__ dout) {
    constexpr int PPT = NP / T;
    int b = blockIdx.x;
    int tid = threadIdx.x;
    int lane = tid & 31, wid = tid >> 5;
    constexpr int NWARPS = T / 32;

    const float* px = xyz + (size_t)b * NP * 3;
    float cx[PPT], cy[PPT], cz[PPT], dist[PPT];
#pragma unroll
    for (int j = 0; j < PPT; j++) {
        int p = tid + j * T;
        cx[j] = px[p * 3 + 0];
        cy[j] = px[p * 3 + 1];
        cz[j] = px[p * 3 + 2];
        dist[j] = 1e10f;
    }

    __shared__ float s_wd[32];
    __shared__ int s_wi[32];
    __shared__ float s_fc[3];
    __shared__ int s_far;

    int far = 0;
    for (int s = 0; s < S; s++) {
        // owner of `far` records the sample and broadcasts its coords
        if ((far % T) == tid) {
            int j = far / T;
            nx[((size_t)b * S + s) * 3 + 0] = cx[j];
            nx[((size_t)b * S + s) * 3 + 1] = cy[j];
            nx[((size_t)b * S + s) * 3 + 2] = cz[j];
            dout[((size_t)b * 3 + 0) * S + s] = cx[j];
            dout[((size_t)b * 3 + 1) * S + s] = cy[j];
            dout[((size_t)b * 3 + 2) * S + s] = cz[j];
            s_fc[0] = cx[j]; s_fc[1] = cy[j]; s_fc[2] = cz[j];
        }
        __syncthreads();
        float fx = s_fc[0], fy = s_fc[1], fz = s_fc[2];

        float bd = -1.0f;
        int bi = 0x7fffffff;
#pragma unroll
        for (int j = 0; j < PPT; j++) {
            float dx = __fadd_rn(cx[j], -fx);
            float dy = __fadd_rn(cy[j], -fy);
            float dz = __fadd_rn(cz[j], -fz);
            float d = sq3(dx, dy, dz);
            float nd = fminf(dist[j], d);
            dist[j] = nd;
            int p = tid + j * T;
            if (nd > bd) { bd = nd; bi = p; }   // j ascending => p ascending keeps first-max
        }
        // warp argmax, tie -> smaller index
#pragma unroll
        for (int off = 16; off > 0; off >>= 1) {
            float od = __shfl_down_sync(0xffffffffu, bd, off);
            int oi = __shfl_down_sync(0xffffffffu, bi, off);
            if (od > bd || (od == bd && oi < bi)) { bd = od; bi = oi; }
        }
        if (lane == 0) { s_wd[wid] = bd; s_wi[wid] = bi; }
        __syncthreads();
        if (wid == 0) {
            float d2 = (lane < NWARPS) ? s_wd[lane] : -2.0f;
            int i2 = (lane < NWARPS) ? s_wi[lane] : 0x7fffffff;
#pragma unroll
            for (int off = 16; off > 0; off >>= 1) {
                float od = __shfl_down_sync(0xffffffffu, d2, off);
                int oi = __shfl_down_sync(0xffffffffu, i2, off);
                if (od > d2 || (od == d2 && oi < i2)) { d2 = od; i2 = oi; }
            }
            if (lane == 0) s_far = i2;
        }
        __syncthreads();
        far = s_far;
    }
}

// ---------------------------------------------------------------------------
// MLP stage: out[k][o] = relu(b[o] + sum_ci W[o][ci] * in[k][ci])
// mapping: lane = k, warp = o-group  => W row is warp-uniform (broadcast load),
// smem rows have odd pitch => conflict-free.
// ---------------------------------------------------------------------------
template <int CI, int CO, int PI, int PO, int NT>
__device__ __forceinline__ void mlp_stage(const float* __restrict__ fin,
                                          float* __restrict__ fo,
                                          const float* __restrict__ W,
                                          const float* __restrict__ Bv, int tid) {
    for (int e = tid; e < 32 * CO; e += NT) {
        int k = e & 31;
        int o = e >> 5;
        const float* w = W + (size_t)o * CI;
        const float* f = fin + k * PI;
        float acc = Bv[o];
#pragma unroll 4
        for (int ci = 0; ci < CI; ci++) acc = fmaf(__ldg(w + ci), f[ci], acc);
        fo[k * PO + o] = fmaxf(acc, 0.0f);
    }
}

// ---------------------------------------------------------------------------
// Fused SA layer: one block (256 thr) per (batch, center).
// warp0: ball query (ordered lowest-index hits, pad with first hit)
// all:   gather -> mlp x3 -> max over K -> write feat (pm) + d_out (transposed)
// ---------------------------------------------------------------------------
template <int NP, int S, int D, int C1, int C2, int C3, int PA, int PB>
__global__ __launch_bounds__(256) void k_sa(const float* __restrict__ xyz,
                                            const float* __restrict__ pts,
                                            const float* __restrict__ cxyz,
                                            const float* __restrict__ W1, const float* __restrict__ B1,
                                            const float* __restrict__ W2, const float* __restrict__ B2,
                                            const float* __restrict__ W3, const float* __restrict__ B3,
                                            float* __restrict__ fout,
                                            float* __restrict__ dout, float r2) {
    constexpr int CIN = D + 3;
    extern __shared__ float smdyn[];
    float* bufA = smdyn;             // [32, PA]
    float* bufB = smdyn + 32 * PA;   // [32, PB]
    __shared__ int nidx[32];
    __shared__ float cen[3];

    int bid = blockIdx.x;
    int b = bid / S;
    int s = bid - b * S;
    int tid = threadIdx.x;

    // ---- ball query (warp 0) ----
    if (tid < 32) {
        int lane = tid;
        float cx = cxyz[((size_t)b * S + s) * 3 + 0];
        float cy = cxyz[((size_t)b * S + s) * 3 + 1];
        float cz = cxyz[((size_t)b * S + s) * 3 + 2];
        if (lane == 0) { cen[0] = cx; cen[1] = cy; cen[2] = cz; }
        float smc = sq3(cx, cy, cz);
        const float* px = xyz + (size_t)b * NP * 3;
        int cnt = 0;
        for (int base = 0; base < NP && cnt < 32; base += 32) {
            int p = base + lane;
            float x = px[p * 3 + 0], y = px[p * 3 + 1], z = px[p * 3 + 2];
            float sn = sq3(x, y, z);
            float dot = __fadd_rn(__fadd_rn(__fmul_rn(cx, x), __fmul_rn(cy, y)), __fmul_rn(cz, z));
            float sq = __fadd_rn(__fadd_rn(smc, sn), -__fmul_rn(2.0f, dot));
            bool hit = !(sq > r2);
            unsigned m = __ballot_sync(0xffffffffu, hit);
            if (hit) {
                int pos = cnt + __popc(m & ((1u << lane) - 1u));
                if (pos < 32) nidx[pos] = p;
            }
            cnt += __popc(m);
        }
        if (cnt > 32) cnt = 32;
        __syncwarp();
        int i0 = nidx[0];   // center itself is always a hit => cnt >= 1
        for (int t = cnt + lane; t < 32; t += 32) nidx[t] = i0;
    }
    __syncthreads();

    // ---- gather: [rel_xyz(3), pts(D)] into bufA ----
    float c0 = cen[0], c1 = cen[1], c2 = cen[2];
    for (int e = tid; e < 32 * CIN; e += 256) {
        int k = e / CIN;
        int c = e - k * CIN;
        int p = nidx[k];
        float v;
        if (c < 3) {
            float cc = (c == 0) ? c0 : (c == 1) ? c1 : c2;
            v = __fadd_rn(xyz[((size_t)b * NP + p) * 3 + c], -cc);
        } else {
            v = pts[((size_t)b * NP + p) * D + (c - 3)];
        }
        bufA[k * PA + c] = v;
    }
    __syncthreads();

    mlp_stage<CIN, C1, PA, PB, 256>(bufA, bufB, W1, B1, tid);
    __syncthreads();
    mlp_stage<C1, C2, PB, PA, 256>(bufB, bufA, W2, B2, tid);
    __syncthreads();
    mlp_stage<C2, C3, PA, PB, 256>(bufA, bufB, W3, B3, tid);
    __syncthreads();

    // ---- max over neighbors, dual-layout write ----
    for (int o = tid; o < C3; o += 256) {
        float m = bufB[o];
#pragma unroll
        for (int k = 1; k < 32; k++) m = fmaxf(m, bufB[k * PB + o]);
        fout[((size_t)b * S + s) * C3 + o] = m;
        dout[((size_t)b * C3 + o) * S + s] = m;
    }
}

// ---------------------------------------------------------------------------
extern "C" void kernel_launch(void* const* d_in, const int* in_sizes, int n_in,
                              void* d_out, int out_size) {
    const float* xin = (const float*)d_in[0];
    const float* w1a = (const float*)d_in[1];  const float* b1a = (const float*)d_in[2];
    const float* w1b = (const float*)d_in[3];  const float* b1b = (const float*)d_in[4];
    const float* w1c = (const float*)d_in[5];  const float* b1c = (const float*)d_in[6];
    const float* w2a = (const float*)d_in[7];  const float* b2a = (const float*)d_in[8];
    const float* w2b = (const float*)d_in[9];  const float* b2b = (const float*)d_in[10];
    const float* w2c = (const float*)d_in[11]; const float* b2c = (const float*)d_in[12];
    const float* w3a = (const float*)d_in[13]; const float* b3a = (const float*)d_in[14];
    const float* w3b = (const float*)d_in[15]; const float* b3b = (const float*)d_in[16];
    const float* w3c = (const float*)d_in[17]; const float* b3c = (const float*)d_in[18];
    const float* w4a = (const float*)d_in[19]; const float* b4a = (const float*)d_in[20];
    const float* w4b = (const float*)d_in[21]; const float* b4b = (const float*)d_in[22];
    const float* w4c = (const float*)d_in[23]; const float* b4c = (const float*)d_in[24];
    float* out = (float*)d_out;

    float *p_xyz0, *p_pts0, *p_nx1, *p_f1, *p_nx2, *p_f2, *p_nx3, *p_f3, *p_nx4, *p_f4;
    cudaGetSymbolAddress((void**)&p_xyz0, g_xyz0);
    cudaGetSymbolAddress((void**)&p_pts0, g_pts0);
    cudaGetSymbolAddress((void**)&p_nx1, g_nx1);
    cudaGetSymbolAddress((void**)&p_f1, g_f1);
    cudaGetSymbolAddress((void**)&p_nx2, g_nx2);
    cudaGetSymbolAddress((void**)&p_f2, g_f2);
    cudaGetSymbolAddress((void**)&p_nx3, g_nx3);
    cudaGetSymbolAddress((void**)&p_f3, g_f3);
    cudaGetSymbolAddress((void**)&p_nx4, g_nx4);
    cudaGetSymbolAddress((void**)&p_f4, g_f4);

    // radii squared exactly as JAX computes them (python double, cast to f32)
    float r2_1 = (float)(0.1 * 0.1);
    float r2_2 = (float)(0.2 * 0.2);
    float r2_3 = (float)(0.4 * 0.4);
    float r2_4 = (float)(0.8 * 0.8);

    // dynamic smem sizes
    const int SM1 = 32 * (33 + 65) * 4;    // 12544
    const int SM2 = 32 * (67 + 129) * 4;   // 25088
    const int SM3 = 32 * (131 + 257) * 4;  // 49664
    const int SM4 = 32 * (259 + 513) * 4;  // 98816
    cudaFuncSetAttribute(k_sa<256, 64, 128, 128, 128, 256, 131, 257>,
                         cudaFuncAttributeMaxDynamicSharedMemorySize, SM3);
    cudaFuncSetAttribute(k_sa<64, 16, 256, 256, 256, 512, 259, 513>,
                         cudaFuncAttributeMaxDynamicSharedMemorySize, SM4);

    // stage 0: transpose + output 1
    k_transpose<<<(NBATCH * NPTS0 + 255) / 256, 256>>>(xin, out + O1);

    // layer 1
    k_fps<4096, 1024, 1024><<<NBATCH, 1024>>>(p_xyz0, p_nx1, out + O2);
    k_sa<4096, 1024, 9, 32, 32, 64, 33, 65><<<NBATCH * 1024, 256, SM1>>>(
        p_xyz0, p_pts0, p_nx1, w1a, b1a, w1b, b1b, w1c, b1c, p_f1, out + O6, r2_1);

    // layer 2
    k_fps<1024, 256, 256><<<NBATCH, 256>>>(p_nx1, p_nx2, out + O3);
    k_sa<1024, 256, 64, 64, 64, 128, 67, 129><<<NBATCH * 256, 256, SM2>>>(
        p_nx1, p_f1, p_nx2, w2a, b2a, w2b, b2b, w2c, b2c, p_f2, out + O7, r2_2);

    // layer 3
    k_fps<256, 64, 256><<<NBATCH, 256>>>(p_nx2, p_nx3, out + O4);
    k_sa<256, 64, 128, 128, 128, 256, 131, 257><<<NBATCH * 64, 256, SM3>>>(
        p_nx2, p_f2, p_nx3, w3a, b3a, w3b, b3b, w3c, b3c, p_f3, out + O8, r2_3);

    // layer 4
    k_fps<64, 16, 64><<<NBATCH, 64>>>(p_nx3, p_nx4, out + O5);
    k_sa<64, 16, 256, 256, 256, 512, 259, 513><<<NBATCH * 16, 256, SM4>>>(
        p_nx3, p_f3, p_nx4, w4a, b4a, w4b, b4b, w4c, b4c, p_f4, out + O9, r2_4);
}

// round 3
// speedup vs baseline: 2.5143x; 2.5143x over previous
#include <cuda_runtime.h>

#define NBATCH 16
#define NPTS0  4096
#define FULLMASK 0xffffffffu

// ---------------- device scratch (no allocations allowed) ------------------
__device__ float g_xyz0[NBATCH * NPTS0 * 3];
__device__ float g_pts0[NBATCH * NPTS0 * 9];
__device__ float g_nx1[NBATCH * 1024 * 3];
__device__ float g_f1 [NBATCH * 1024 * 64];
__device__ float g_nx2[NBATCH * 256 * 3];
__device__ float g_f2 [NBATCH * 256 * 128];
__device__ float g_nx3[NBATCH * 64 * 3];
__device__ float g_f3 [NBATCH * 64 * 256];
__device__ float g_nx4[NBATCH * 16 * 3];
__device__ float g_f4 [NBATCH * 16 * 512];

// ---------------- d_out offsets (float elements) ----------------------------
#define O1 0        // [16,3,4096]
#define O2 196608   // [16,3,1024]
#define O3 245760   // [16,3,256]
#define O4 258048   // [16,3,64]
#define O5 261120   // [16,3,16]
#define O6 261888   // [16,64,1024]
#define O7 1310464  // [16,128,256]
#define O8 1834752  // [16,256,64]
#define O9 2096896  // [16,512,16]

__device__ __forceinline__ float sq3(float a, float b, float c) {
    return __fadd_rn(__fadd_rn(__fmul_rn(a, a), __fmul_rn(b, b)), __fmul_rn(c, c));
}

// ---------------------------------------------------------------------------
// Transpose [B,9,N] -> point-major scratch; also emits output region 1.
// ---------------------------------------------------------------------------
__global__ void k_transpose(const float* __restrict__ in, float* __restrict__ out1) {
    int i = blockIdx.x * blockDim.x + threadIdx.x;
    if (i >= NBATCH * NPTS0) return;
    int b = i >> 12;
    int n = i & (NPTS0 - 1);
    const float* src = in + (size_t)b * 9 * NPTS0;
    float v[9];
#pragma unroll
    for (int c = 0; c < 9; c++) v[c] = src[c * NPTS0 + n];
#pragma unroll
    for (int c = 0; c < 9; c++) g_pts0[(size_t)i * 9 + c] = v[c];
#pragma unroll
    for (int c = 0; c < 3; c++) g_xyz0[(size_t)i * 3 + c] = v[c];
#pragma unroll
    for (int c = 0; c < 3; c++) out1[((size_t)b * 3 + c) * NPTS0 + n] = v[c];
}

// ---------------------------------------------------------------------------
// FPS: one block per batch. Coords in regs + smem (for far-point broadcast).
// One __syncthreads per iteration: warp argmax via redux.sync, packed u64 key
// per warp in double-buffered smem, every warp redundantly reduces the keys.
// ---------------------------------------------------------------------------
template <int NP, int S, int T>
__global__ __launch_bounds__(T) void k_fps(const float* __restrict__ xyz,
                                           float* __restrict__ nx,
                                           float* __restrict__ dout) {
    constexpr int PPT = NP / T;
    constexpr int NW = T / 32;
    extern __shared__ float fsm[];
    float* sx = fsm;
    float* sy = fsm + NP;
    float* sz = fsm + 2 * NP;
    __shared__ unsigned long long skey[2][32];

    int b = blockIdx.x, tid = threadIdx.x;
    int lane = tid & 31, wd = tid >> 5;
    const float* px = xyz + (size_t)b * NP * 3;

    float cx[PPT], cy[PPT], cz[PPT], dist[PPT];
#pragma unroll
    for (int j = 0; j < PPT; j++) {
        int p = tid + j * T;
        float x = px[p * 3 + 0], y = px[p * 3 + 1], z = px[p * 3 + 2];
        cx[j] = x; cy[j] = y; cz[j] = z;
        dist[j] = 1e10f;
        sx[p] = x; sy[p] = y; sz[p] = z;
    }
    __syncthreads();

    int far = 0;
    for (int s = 0; s < S; s++) {
        float fx = sx[far], fy = sy[far], fz = sz[far];
        if (tid == 0) {
            nx[((size_t)b * S + s) * 3 + 0] = fx;
            nx[((size_t)b * S + s) * 3 + 1] = fy;
            nx[((size_t)b * S + s) * 3 + 2] = fz;
            dout[((size_t)b * 3 + 0) * S + s] = fx;
            dout[((size_t)b * 3 + 1) * S + s] = fy;
            dout[((size_t)b * 3 + 2) * S + s] = fz;
        }
        float bd = 0.0f; int bi = 0;
#pragma unroll
        for (int j = 0; j < PPT; j++) {
            float dx = __fadd_rn(cx[j], -fx);
            float dy = __fadd_rn(cy[j], -fy);
            float dz = __fadd_rn(cz[j], -fz);
            float d = sq3(dx, dy, dz);
            float nd = fminf(dist[j], d);
            dist[j] = nd;
            if (j == 0) { bd = nd; bi = tid; }
            else if (nd > bd) { bd = nd; bi = tid + j * T; }
        }
        // warp argmax (dists >= 0 so float bits are order-preserving)
        unsigned mb = __reduce_max_sync(FULLMASK, __float_as_uint(bd));
        unsigned cand = (__float_as_uint(bd) == mb) ? (unsigned)bi : 0xffffffffu;
        unsigned mi = __reduce_min_sync(FULLMASK, cand);
        if (lane == 0)
            skey[s & 1][wd] = ((unsigned long long)mb << 32) |
                              (unsigned long long)(0xffffffffu - mi);
        __syncthreads();
        unsigned long long k2 = (lane < NW) ? skey[s & 1][lane] : 0ull;
#pragma unroll
        for (int off = 16; off > 0; off >>= 1) {
            unsigned long long o = __shfl_down_sync(FULLMASK, k2, off);
            if (o > k2) k2 = o;
        }
        k2 = __shfl_sync(FULLMASK, k2, 0);
        far = (int)(0xffffffffu - (unsigned)(k2 & 0xffffffffu));
    }
}

// ---------------------------------------------------------------------------
// MLP stage (middle): weights staged in smem chunks of 16 ci-cols (pitch 20),
// lane = neighbor k, each thread accumulates OB = CO/8 outputs in registers.
// Inner step: 1 lane-distinct LDS.128 (f) + OB broadcast LDS.128 (w) + 4*OB FMA.
// ---------------------------------------------------------------------------
template <int CIa, int CIp, int CO, int PI, int PO>
__device__ __forceinline__ void mlp_mid(const float* __restrict__ fin,
                                        float* __restrict__ fo,
                                        float* __restrict__ wsm,
                                        const float* __restrict__ W,
                                        const float* __restrict__ Bv, int tid) {
    constexpr int OB = CO / 8;
    int lane = tid & 31;
    int obase = (tid >> 5) * OB;
    float acc[OB];
#pragma unroll
    for (int j = 0; j < OB; j++) acc[j] = __ldg(Bv + obase + j);
    const float* frow = fin + lane * PI;
    for (int ci0 = 0; ci0 < CIp; ci0 += 16) {
        __syncthreads();
        for (int e = tid; e < CO * 16; e += 256) {
            int o = e >> 4, g = e & 15;
            int ci = ci0 + g;
            wsm[o * 20 + g] = (ci < CIa) ? __ldg(W + o * CIa + ci) : 0.0f;
        }
        __syncthreads();
        int gmax = (CIp - ci0 < 16) ? (CIp - ci0) : 16;
        for (int g = 0; g < gmax; g += 4) {
            float4 f4 = *(const float4*)(frow + ci0 + g);
            const float* wb = wsm + obase * 20 + g;
#pragma unroll
            for (int j = 0; j < OB; j++) {
                float4 w4 = *(const float4*)(wb + j * 20);
                acc[j] = fmaf(w4.x, f4.x, acc[j]);
                acc[j] = fmaf(w4.y, f4.y, acc[j]);
                acc[j] = fmaf(w4.z, f4.z, acc[j]);
                acc[j] = fmaf(w4.w, f4.w, acc[j]);
            }
        }
    }
    float* orow = fo + lane * PO + obase;
#pragma unroll
    for (int j = 0; j < OB; j++) orow[j] = fmaxf(acc[j], 0.0f);
}

// Last stage: same compute, then max over the 32 neighbors (lanes) in
// registers via warp shuffle; lane 0 writes both output layouts.
template <int CIa, int CIp, int CO, int PI>
__device__ __forceinline__ void mlp_last(const float* __restrict__ fin,
                                         float* __restrict__ wsm,
                                         const float* __restrict__ W,
                                         const float* __restrict__ Bv,
                                         float* __restrict__ foutp,
                                         float* __restrict__ doutp,
                                         int S_, int tid) {
    constexpr int OB = CO / 8;
    int lane = tid & 31;
    int obase = (tid >> 5) * OB;
    float acc[OB];
#pragma unroll
    for (int j = 0; j < OB; j++) acc[j] = __ldg(Bv + obase + j);
    const float* frow = fin + lane * PI;
    for (int ci0 = 0; ci0 < CIp; ci0 += 16) {
        __syncthreads();
        for (int e = tid; e < CO * 16; e += 256) {
            int o = e >> 4, g = e & 15;
            int ci = ci0 + g;
            wsm[o * 20 + g] = (ci < CIa) ? __ldg(W + o * CIa + ci) : 0.0f;
        }
        __syncthreads();
        int gmax = (CIp - ci0 < 16) ? (CIp - ci0) : 16;
        for (int g = 0; g < gmax; g += 4) {
            float4 f4 = *(const float4*)(frow + ci0 + g);
            const float* wb = wsm + obase * 20 + g;
#pragma unroll
            for (int j = 0; j < OB; j++) {
                float4 w4 = *(const float4*)(wb + j * 20);
                acc[j] = fmaf(w4.x, f4.x, acc[j]);
                acc[j] = fmaf(w4.y, f4.y, acc[j]);
                acc[j] = fmaf(w4.z, f4.z, acc[j]);
                acc[j] = fmaf(w4.w, f4.w, acc[j]);
            }
        }
    }
#pragma unroll
    for (int j = 0; j < OB; j++) {
        float m = fmaxf(acc[j], 0.0f);
#pragma unroll
        for (int off = 16; off > 0; off >>= 1)
            m = fmaxf(m, __shfl_xor_sync(FULLMASK, m, off));
        if (lane == 0) {
            int o = obase + j;
            foutp[o] = m;
            doutp[(size_t)o * S_] = m;
        }
    }
}

// ---------------------------------------------------------------------------
// Fused SA layer: one block (256 thr, 8 warps) per (batch, center).
// Multi-warp ball query (order-preserving chunked merge), gather, MLP x3.
// ---------------------------------------------------------------------------
template <int NP, int S, int D, int C1, int C2, int C3, int CINp, int PA, int NWQ>
__global__ __launch_bounds__(256) void k_sa(const float* __restrict__ xyz,
                                            const float* __restrict__ pts,
                                            const float* __restrict__ cxyz,
                                            const float* __restrict__ W1, const float* __restrict__ B1,
                                            const float* __restrict__ W2, const float* __restrict__ B2,
                                            const float* __restrict__ W3, const float* __restrict__ B3,
                                            float* __restrict__ fout,
                                            float* __restrict__ dout, float r2) {
    constexpr int CIN = D + 3;
    extern __shared__ float smdyn[];
    float* bufA = smdyn;            // [32, PA]
    float* bufB = smdyn + 32 * PA;  // [32, PA]
    float* wsm  = smdyn + 64 * PA;  // [COmax, 20]
    __shared__ int hits[8][32];
    __shared__ int cnts[8];
    __shared__ int nidx[32];
    __shared__ float cen[3];

    int bid = blockIdx.x;
    int b = bid / S;
    int s = bid - b * S;
    int tid = threadIdx.x, lane = tid & 31, wd = tid >> 5;

    float cx = __ldg(&cxyz[((size_t)b * S + s) * 3 + 0]);
    float cy = __ldg(&cxyz[((size_t)b * S + s) * 3 + 1]);
    float cz = __ldg(&cxyz[((size_t)b * S + s) * 3 + 2]);
    if (tid == 0) { cen[0] = cx; cen[1] = cy; cen[2] = cz; }

    // ---- ball query: NWQ warps scan disjoint ordered chunks ----
    if (wd < NWQ) {
        constexpr int CHUNK = NP / NWQ;
        float smc = sq3(cx, cy, cz);
        const float* px = xyz + (size_t)b * NP * 3;
        int cnt = 0;
        for (int base = wd * CHUNK; base < (wd + 1) * CHUNK; base += 32) {
            int p = base + lane;
            float x = px[p * 3 + 0], y = px[p * 3 + 1], z = px[p * 3 + 2];
            float sn = sq3(x, y, z);
            float dot = __fadd_rn(__fadd_rn(__fmul_rn(cx, x), __fmul_rn(cy, y)), __fmul_rn(cz, z));
            float sq = __fadd_rn(__fadd_rn(smc, sn), -__fmul_rn(2.0f, dot));
            bool hit = !(sq > r2);
            unsigned m = __ballot_sync(FULLMASK, hit);
            if (hit) {
                int pos = cnt + __popc(m & ((1u << lane) - 1u));
                if (pos < 32) hits[wd][pos] = p;
            }
            cnt += __popc(m);
            if (cnt >= 32) break;
        }
        if (lane == 0) cnts[wd] = (cnt < 32) ? cnt : 32;
    }
    __syncthreads();
    // ---- merge (warp 0), preserves ascending index order; pad with first hit
    if (tid < 32) {
        int total = 0;
#pragma unroll
        for (int w2 = 0; w2 < NWQ; w2++) {
            int c = cnts[w2];
            int take = (c < 32 - total) ? c : (32 - total);
            if (lane < take) nidx[total + lane] = hits[w2][lane];
            total += take;
        }
        __syncwarp();
        int i0 = nidx[0];
        if (lane >= total) nidx[lane] = i0;
    }
    __syncthreads();

    // ---- gather: [rel_xyz(3), pts(D), zero-pad] into bufA ----
    float c0 = cen[0], c1 = cen[1], c2 = cen[2];
    for (int e = tid; e < 32 * CINp; e += 256) {
        int k = e / CINp;
        int c = e - k * CINp;
        int p = nidx[k];
        float v = 0.0f;
        if (c < 3) {
            float cc = (c == 0) ? c0 : (c == 1) ? c1 : c2;
            v = __fadd_rn(xyz[((size_t)b * NP + p) * 3 + c], -cc);
        } else if (c < CIN) {
            v = pts[((size_t)b * NP + p) * D + (c - 3)];
        }
        bufA[k * PA + c] = v;
    }
    // (stage-1's leading __syncthreads covers gather completion)

    mlp_mid<CIN, CINp, C1, PA, PA>(bufA, bufB, wsm, W1, B1, tid);
    mlp_mid<C1, C1, C2, PA, PA>(bufB, bufA, wsm, W2, B2, tid);
    mlp_last<C2, C2, C3, PA>(bufA, wsm, W3, B3,
                             fout + ((size_t)b * S + s) * C3,
                             dout + (size_t)b * C3 * S + s, S, tid);
}

// ---------------------------------------------------------------------------
extern "C" void kernel_launch(void* const* d_in, const int* in_sizes, int n_in,
                              void* d_out, int out_size) {
    const float* xin = (const float*)d_in[0];
    const float* w1a = (const float*)d_in[1];  const float* b1a = (const float*)d_in[2];
    const float* w1b = (const float*)d_in[3];  const float* b1b = (const float*)d_in[4];
    const float* w1c = (const float*)d_in[5];  const float* b1c = (const float*)d_in[6];
    const float* w2a = (const float*)d_in[7];  const float* b2a = (const float*)d_in[8];
    const float* w2b = (const float*)d_in[9];  const float* b2b = (const float*)d_in[10];
    const float* w2c = (const float*)d_in[11]; const float* b2c = (const float*)d_in[12];
    const float* w3a = (const float*)d_in[13]; const float* b3a = (const float*)d_in[14];
    const float* w3b = (const float*)d_in[15]; const float* b3b = (const float*)d_in[16];
    const float* w3c = (const float*)d_in[17]; const float* b3c = (const float*)d_in[18];
    const float* w4a = (const float*)d_in[19]; const float* b4a = (const float*)d_in[20];
    const float* w4b = (const float*)d_in[21]; const float* b4b = (const float*)d_in[22];
    const float* w4c = (const float*)d_in[23]; const float* b4c = (const float*)d_in[24];
    float* out = (float*)d_out;

    float *p_xyz0, *p_pts0, *p_nx1, *p_f1, *p_nx2, *p_f2, *p_nx3, *p_f3, *p_nx4, *p_f4;
    cudaGetSymbolAddress((void**)&p_xyz0, g_xyz0);
    cudaGetSymbolAddress((void**)&p_pts0, g_pts0);
    cudaGetSymbolAddress((void**)&p_nx1, g_nx1);
    cudaGetSymbolAddress((void**)&p_f1, g_f1);
    cudaGetSymbolAddress((void**)&p_nx2, g_nx2);
    cudaGetSymbolAddress((void**)&p_f2, g_f2);
    cudaGetSymbolAddress((void**)&p_nx3, g_nx3);
    cudaGetSymbolAddress((void**)&p_f3, g_f3);
    cudaGetSymbolAddress((void**)&p_nx4, g_nx4);
    cudaGetSymbolAddress((void**)&p_f4, g_f4);

    float r2_1 = (float)(0.1 * 0.1);
    float r2_2 = (float)(0.2 * 0.2);
    float r2_3 = (float)(0.4 * 0.4);
    float r2_4 = (float)(0.8 * 0.8);

    // dynamic smem: 64*PA + COmax*20 floats
    const int SM1 = (64 * 36 + 64 * 20) * 4;    // 14336
    const int SM2 = (64 * 68 + 128 * 20) * 4;   // 27648
    const int SM3 = (64 * 132 + 256 * 20) * 4;  // 54272
    const int SM4 = (64 * 260 + 512 * 20) * 4;  // 107520
    cudaFuncSetAttribute(k_fps<4096, 1024, 512>,
                         cudaFuncAttributeMaxDynamicSharedMemorySize, 3 * 4096 * 4);
    cudaFuncSetAttribute(k_sa<256, 64, 128, 128, 128, 256, 132, 132, 8>,
                         cudaFuncAttributeMaxDynamicSharedMemorySize, SM3);
    cudaFuncSetAttribute(k_sa<64, 16, 256, 256, 256, 512, 260, 260, 2>,
                         cudaFuncAttributeMaxDynamicSharedMemorySize, SM4);

    // stage 0: transpose + output 1
    k_transpose<<<(NBATCH * NPTS0 + 255) / 256, 256>>>(xin, out + O1);

    // layer 1
    k_fps<4096, 1024, 512><<<NBATCH, 512, 3 * 4096 * 4>>>(p_xyz0, p_nx1, out + O2);
    k_sa<4096, 1024, 9, 32, 32, 64, 12, 36, 8><<<NBATCH * 1024, 256, SM1>>>(
        p_xyz0, p_pts0, p_nx1, w1a, b1a, w1b, b1b, w1c, b1c, p_f1, out + O6, r2_1);

    // layer 2
    k_fps<1024, 256, 256><<<NBATCH, 256, 3 * 1024 * 4>>>(p_nx1, p_nx2, out + O3);
    k_sa<1024, 256, 64, 64, 64, 128, 68, 68, 8><<<NBATCH * 256, 256, SM2>>>(
        p_nx1, p_f1, p_nx2, w2a, b2a, w2b, b2b, w2c, b2c, p_f2, out + O7, r2_2);

    // layer 3
    k_fps<256, 64, 256><<<NBATCH, 256, 3 * 256 * 4>>>(p_nx2, p_nx3, out + O4);
    k_sa<256, 64, 128, 128, 128, 256, 132, 132, 8><<<NBATCH * 64, 256, SM3>>>(
        p_nx2, p_f2, p_nx3, w3a, b3a, w3b, b3b, w3c, b3c, p_f3, out + O8, r2_3);

    // layer 4
    k_fps<64, 16, 64><<<NBATCH, 64, 3 * 64 * 4>>>(p_nx3, p_nx4, out + O5);
    k_sa<64, 16, 256, 256, 256, 512, 260, 260, 2><<<NBATCH * 16, 256, SM4>>>(
        p_nx3, p_f3, p_nx4, w4a, b4a, w4b, b4b, w4c, b4c, p_f4, out + O9, r2_4);
}

// round 4
// speedup vs baseline: 2.5204x; 1.0024x over previous
#include <cuda_runtime.h>

#define NBATCH 16
#define NPTS0  4096
#define FULLMASK 0xffffffffu

// ---------------- device scratch (no allocations allowed) ------------------
__device__ float4 g_xyz0[NBATCH * NPTS0];      // x,y,z,|p|^2
__device__ float  g_pts0[NBATCH * NPTS0 * 9];
__device__ float4 g_nx1[NBATCH * 1024];
__device__ float  g_f1 [NBATCH * 1024 * 64];
__device__ float4 g_nx2[NBATCH * 256];
__device__ float  g_f2 [NBATCH * 256 * 128];
__device__ float4 g_nx3[NBATCH * 64];
__device__ float  g_f3 [NBATCH * 64 * 256];
__device__ float4 g_nx4[NBATCH * 16];
__device__ float  g_f4 [NBATCH * 16 * 512];

// ---------------- d_out offsets (float elements) ----------------------------
#define O1 0        // [16,3,4096]
#define O2 196608   // [16,3,1024]
#define O3 245760   // [16,3,256]
#define O4 258048   // [16,3,64]
#define O5 261120   // [16,3,16]
#define O6 261888   // [16,64,1024]
#define O7 1310464  // [16,128,256]
#define O8 1834752  // [16,256,64]
#define O9 2096896  // [16,512,16]

__device__ __forceinline__ float sq3(float a, float b, float c) {
    return __fadd_rn(__fadd_rn(__fmul_rn(a, a), __fmul_rn(b, b)), __fmul_rn(c, c));
}

// ---------------------------------------------------------------------------
// Transpose [B,9,N] -> point-major scratch (+ precomputed |p|^2), emits out1.
// ---------------------------------------------------------------------------
__global__ void k_transpose(const float* __restrict__ in, float* __restrict__ out1) {
    int i = blockIdx.x * blockDim.x + threadIdx.x;
    if (i >= NBATCH * NPTS0) return;
    int b = i >> 12;
    int n = i & (NPTS0 - 1);
    const float* src = in + (size_t)b * 9 * NPTS0;
    float v[9];
#pragma unroll
    for (int c = 0; c < 9; c++) v[c] = src[c * NPTS0 + n];
#pragma unroll
    for (int c = 0; c < 9; c++) g_pts0[(size_t)i * 9 + c] = v[c];
    g_xyz0[i] = make_float4(v[0], v[1], v[2], sq3(v[0], v[1], v[2]));
#pragma unroll
    for (int c = 0; c < 3; c++) out1[((size_t)b * 3 + c) * NPTS0 + n] = v[c];
}

// ---------------------------------------------------------------------------
// FPS body (shared by standalone kernel and sa-embedded tail blocks).
// One barrier per iteration; warp redux.sync argmax -> u64 key in smem ->
// every thread redundantly tree-reduces NW keys in registers (no broadcast).
// ---------------------------------------------------------------------------
template <int NPf, int Sf, int NW>
__device__ void fps_body(const float4* __restrict__ xyz, float4* __restrict__ nx,
                         float* __restrict__ dout, int b, int tid, float4* sc4) {
    constexpr int T = NW * 32;
    constexpr int PPT = (NPf + T - 1) / T;
    constexpr bool GUARD = (NPf % T) != 0;
    __shared__ unsigned long long skey[2][NW];
    int lane = tid & 31, wd = tid >> 5;
    const float4* px = xyz + (size_t)b * NPf;

    float cx[PPT], cy[PPT], cz[PPT], dist[PPT];
#pragma unroll
    for (int j = 0; j < PPT; j++) {
        int p = tid + j * T;
        dist[j] = 1e10f;
        cx[j] = 0.f; cy[j] = 0.f; cz[j] = 0.f;
        if (!GUARD || p < NPf) {
            float4 v = px[p];
            sc4[p] = v;
            cx[j] = v.x; cy[j] = v.y; cz[j] = v.z;
        }
    }
    __syncthreads();

    int far = 0;
    for (int s = 0; s < Sf; s++) {
        float4 f = sc4[far];
        if (tid == 0) {
            nx[(size_t)b * Sf + s] = f;
            dout[((size_t)b * 3 + 0) * Sf + s] = f.x;
            dout[((size_t)b * 3 + 1) * Sf + s] = f.y;
            dout[((size_t)b * 3 + 2) * Sf + s] = f.z;
        }
        unsigned bb = 0u, bi = 0xffffffffu;
#pragma unroll
        for (int j = 0; j < PPT; j++) {
            int p = tid + j * T;
            if (!GUARD || p < NPf) {
                float dx = __fadd_rn(cx[j], -f.x);
                float dy = __fadd_rn(cy[j], -f.y);
                float dz = __fadd_rn(cz[j], -f.z);
                float d = sq3(dx, dy, dz);
                float nd = fminf(dist[j], d);
                dist[j] = nd;
                unsigned nb = __float_as_uint(nd);   // dist >= 0 -> bits order-preserving
                if (nb > bb || (nb == bb && (unsigned)p < bi)) { bb = nb; bi = (unsigned)p; }
            }
        }
        unsigned mb = __reduce_max_sync(FULLMASK, bb);
        unsigned cand = (bb == mb) ? bi : 0xffffffffu;
        unsigned mi = __reduce_min_sync(FULLMASK, cand);
        if (lane == 0)
            skey[s & 1][wd] = ((unsigned long long)mb << 32) |
                              (unsigned long long)(0xffffffffu - mi);
        __syncthreads();
        unsigned long long best = skey[s & 1][0];
#pragma unroll
        for (int i = 1; i < NW; i++) {
            unsigned long long o = skey[s & 1][i];
            if (o > best) best = o;
        }
        far = (int)(0xffffffffu - (unsigned)(best & 0xffffffffu));
    }
}

template <int NPf, int Sf, int NW>
__global__ __launch_bounds__(NW * 32) void k_fps(const float4* __restrict__ xyz,
                                                 float4* __restrict__ nx,
                                                 float* __restrict__ dout) {
    extern __shared__ float smdyn[];
    fps_body<NPf, Sf, NW>(xyz, nx, dout, blockIdx.x, threadIdx.x, (float4*)smdyn);
}

// ---------------------------------------------------------------------------
// MLP stage (middle): weights staged in smem chunks of 16 ci-cols (pitch 20),
// lane = neighbor k, each thread accumulates OB = CO/8 outputs in registers.
// ---------------------------------------------------------------------------
template <int CIa, int CIp, int CO, int PI, int PO>
__device__ __forceinline__ void mlp_mid(const float* __restrict__ fin,
                                        float* __restrict__ fo,
                                        float* __restrict__ wsm,
                                        const float* __restrict__ W,
                                        const float* __restrict__ Bv, int tid) {
    constexpr int OB = CO / 8;
    int lane = tid & 31;
    int obase = (tid >> 5) * OB;
    float acc[OB];
#pragma unroll
    for (int j = 0; j < OB; j++) acc[j] = __ldg(Bv + obase + j);
    const float* frow = fin + lane * PI;
    for (int ci0 = 0; ci0 < CIp; ci0 += 16) {
        __syncthreads();
        for (int e = tid; e < CO * 16; e += 256) {
            int o = e >> 4, g = e & 15;
            int ci = ci0 + g;
            wsm[o * 20 + g] = (ci < CIa) ? __ldg(W + o * CIa + ci) : 0.0f;
        }
        __syncthreads();
        int gmax = (CIp - ci0 < 16) ? (CIp - ci0) : 16;
        for (int g = 0; g < gmax; g += 4) {
            float4 f4 = *(const float4*)(frow + ci0 + g);
            const float* wb = wsm + obase * 20 + g;
#pragma unroll
            for (int j = 0; j < OB; j++) {
                float4 w4 = *(const float4*)(wb + j * 20);
                acc[j] = fmaf(w4.x, f4.x, acc[j]);
                acc[j] = fmaf(w4.y, f4.y, acc[j]);
                acc[j] = fmaf(w4.z, f4.z, acc[j]);
                acc[j] = fmaf(w4.w, f4.w, acc[j]);
            }
        }
    }
    float* orow = fo + lane * PO + obase;
#pragma unroll
    for (int j = 0; j < OB; j++) orow[j] = fmaxf(acc[j], 0.0f);
}

// Last stage: compute, then max over 32 neighbors via warp shuffle.
template <int CIa, int CIp, int CO, int PI>
__device__ __forceinline__ void mlp_last(const float* __restrict__ fin,
                                         float* __restrict__ wsm,
                                         const float* __restrict__ W,
                                         const float* __restrict__ Bv,
                                         float* __restrict__ foutp,
                                         float* __restrict__ doutp,
                                         int S_, int tid) {
    constexpr int OB = CO / 8;
    int lane = tid & 31;
    int obase = (tid >> 5) * OB;
    float acc[OB];
#pragma unroll
    for (int j = 0; j < OB; j++) acc[j] = __ldg(Bv + obase + j);
    const float* frow = fin + lane * PI;
    for (int ci0 = 0; ci0 < CIp; ci0 += 16) {
        __syncthreads();
        for (int e = tid; e < CO * 16; e += 256) {
            int o = e >> 4, g = e & 15;
            int ci = ci0 + g;
            wsm[o * 20 + g] = (ci < CIa) ? __ldg(W + o * CIa + ci) : 0.0f;
        }
        __syncthreads();
        int gmax = (CIp - ci0 < 16) ? (CIp - ci0) : 16;
        for (int g = 0; g < gmax; g += 4) {
            float4 f4 = *(const float4*)(frow + ci0 + g);
            const float* wb = wsm + obase * 20 + g;
#pragma unroll
            for (int j = 0; j < OB; j++) {
                float4 w4 = *(const float4*)(wb + j * 20);
                acc[j] = fmaf(w4.x, f4.x, acc[j]);
                acc[j] = fmaf(w4.y, f4.y, acc[j]);
                acc[j] = fmaf(w4.z, f4.z, acc[j]);
                acc[j] = fmaf(w4.w, f4.w, acc[j]);
            }
        }
    }
#pragma unroll
    for (int j = 0; j < OB; j++) {
        float m = fmaxf(acc[j], 0.0f);
#pragma unroll
        for (int off = 16; off > 0; off >>= 1)
            m = fmaxf(m, __shfl_xor_sync(FULLMASK, m, off));
        if (lane == 0) {
            int o = obase + j;
            foutp[o] = m;
            doutp[(size_t)o * S_] = m;
        }
    }
}

// ---------------------------------------------------------------------------
// Fused SA layer (+ embedded FPS for the NEXT layer in the first NBATCH
// blocks — fps(n+1) only depends on this layer's centers, so it overlaps).
// ---------------------------------------------------------------------------
template <int NP, int S, int D, int C1, int C2, int C3, int CINp, int PA,
          int NWQ, int SOUT>
__global__ __launch_bounds__(256) void k_sa(const float4* __restrict__ xyz4,
                                            const float* __restrict__ pts,
                                            const float4* __restrict__ cxyz,
                                            const float* __restrict__ W1, const float* __restrict__ B1,
                                            const float* __restrict__ W2, const float* __restrict__ B2,
                                            const float* __restrict__ W3, const float* __restrict__ B3,
                                            float* __restrict__ fout,
                                            float* __restrict__ dout, float r2,
                                            float4* __restrict__ nxout,
                                            float* __restrict__ dout2) {
    constexpr int CIN = D + 3;
    extern __shared__ float smdyn[];
    int bid = blockIdx.x;
    if constexpr (SOUT > 0) {
        if (bid < NBATCH) {   // embedded FPS for next layer, scheduled first
            fps_body<S, SOUT, 8>(cxyz, nxout, dout2, bid, threadIdx.x, (float4*)smdyn);
            return;
        }
        bid -= NBATCH;
    }

    float* bufA = smdyn;            // [32, PA]
    float* bufB = smdyn + 32 * PA;  // [32, PA]
    float* wsm  = smdyn + 64 * PA;  // [COmax, 20]
    __shared__ int hits[8][32];
    __shared__ int cnts[8];
    __shared__ int nidx[32];
    __shared__ float cen[3];

    int b = bid / S;
    int s = bid - b * S;
    int tid = threadIdx.x, lane = tid & 31, wd = tid >> 5;

    float4 cv = __ldg(&cxyz[(size_t)b * S + s]);
    float cx = cv.x, cy = cv.y, cz = cv.z, smc = cv.w;
    if (tid == 0) { cen[0] = cx; cen[1] = cy; cen[2] = cz; }

    // ---- ball query: NWQ warps scan disjoint ordered chunks ----
    if (wd < NWQ) {
        constexpr int CHUNK = NP / NWQ;
        const float4* px = xyz4 + (size_t)b * NP;
        int cnt = 0;
        for (int base = wd * CHUNK; base < (wd + 1) * CHUNK; base += 32) {
            int p = base + lane;
            float4 v = __ldg(&px[p]);
            float dot = __fadd_rn(__fadd_rn(__fmul_rn(cx, v.x), __fmul_rn(cy, v.y)),
                                  __fmul_rn(cz, v.z));
            float sq = __fadd_rn(__fadd_rn(smc, v.w), -__fmul_rn(2.0f, dot));
            bool hit = !(sq > r2);
            unsigned m = __ballot_sync(FULLMASK, hit);
            if (hit) {
                int pos = cnt + __popc(m & ((1u << lane) - 1u));
                if (pos < 32) hits[wd][pos] = p;
            }
            cnt += __popc(m);
            if (cnt >= 32) break;
        }
        if (lane == 0) cnts[wd] = (cnt < 32) ? cnt : 32;
    }
    __syncthreads();
    // ---- merge (warp 0), ascending index order; pad with first hit ----
    if (tid < 32) {
        int total = 0;
#pragma unroll
        for (int w2 = 0; w2 < NWQ; w2++) {
            int c = cnts[w2];
            int take = (c < 32 - total) ? c : (32 - total);
            if (lane < take) nidx[total + lane] = hits[w2][lane];
            total += take;
        }
        __syncwarp();
        int i0 = nidx[0];
        if (lane >= total) nidx[lane] = i0;
    }
    __syncthreads();

    // ---- gather: [rel_xyz(3), pts(D), zero-pad] into bufA ----
    float c0 = cen[0], c1 = cen[1], c2 = cen[2];
    for (int e = tid; e < 32 * CINp; e += 256) {
        int k = e / CINp;
        int c = e - k * CINp;
        int p = nidx[k];
        float v = 0.0f;
        if (c < 3) {
            float cc = (c == 0) ? c0 : (c == 1) ? c1 : c2;
            const float* xf = (const float*)(xyz4 + (size_t)b * NP + p);
            v = __fadd_rn(xf[c], -cc);
        } else if (c < CIN) {
            v = pts[((size_t)b * NP + p) * D + (c - 3)];
        }
        bufA[k * PA + c] = v;
    }
    // (stage-1's leading __syncthreads covers gather completion)

    mlp_mid<CIN, CINp, C1, PA, PA>(bufA, bufB, wsm, W1, B1, tid);
    mlp_mid<C1, C1, C2, PA, PA>(bufB, bufA, wsm, W2, B2, tid);
    mlp_last<C2, C2, C3, PA>(bufA, wsm, W3, B3,
                             fout + ((size_t)b * S + s) * C3,
                             dout + (size_t)b * C3 * S + s, S, tid);
}

// ---------------------------------------------------------------------------
extern "C" void kernel_launch(void* const* d_in, const int* in_sizes, int n_in,
                              void* d_out, int out_size) {
    const float* xin = (const float*)d_in[0];
    const float* w1a = (const float*)d_in[1];  const float* b1a = (const float*)d_in[2];
    const float* w1b = (const float*)d_in[3];  const float* b1b = (const float*)d_in[4];
    const float* w1c = (const float*)d_in[5];  const float* b1c = (const float*)d_in[6];
    const float* w2a = (const float*)d_in[7];  const float* b2a = (const float*)d_in[8];
    const float* w2b = (const float*)d_in[9];  const float* b2b = (const float*)d_in[10];
    const float* w2c = (const float*)d_in[11]; const float* b2c = (const float*)d_in[12];
    const float* w3a = (const float*)d_in[13]; const float* b3a = (const float*)d_in[14];
    const float* w3b = (const float*)d_in[15]; const float* b3b = (const float*)d_in[16];
    const float* w3c = (const float*)d_in[17]; const float* b3c = (const float*)d_in[18];
    const float* w4a = (const float*)d_in[19]; const float* b4a = (const float*)d_in[20];
    const float* w4b = (const float*)d_in[21]; const float* b4b = (const float*)d_in[22];
    const float* w4c = (const float*)d_in[23]; const float* b4c = (const float*)d_in[24];
    float* out = (float*)d_out;

    float4 *p_xyz0, *p_nx1, *p_nx2, *p_nx3, *p_nx4;
    float *p_pts0, *p_f1, *p_f2, *p_f3, *p_f4;
    cudaGetSymbolAddress((void**)&p_xyz0, g_xyz0);
    cudaGetSymbolAddress((void**)&p_pts0, g_pts0);
    cudaGetSymbolAddress((void**)&p_nx1, g_nx1);
    cudaGetSymbolAddress((void**)&p_f1, g_f1);
    cudaGetSymbolAddress((void**)&p_nx2, g_nx2);
    cudaGetSymbolAddress((void**)&p_f2, g_f2);
    cudaGetSymbolAddress((void**)&p_nx3, g_nx3);
    cudaGetSymbolAddress((void**)&p_f3, g_f3);
    cudaGetSymbolAddress((void**)&p_nx4, g_nx4);
    cudaGetSymbolAddress((void**)&p_f4, g_f4);

    float r2_1 = (float)(0.1 * 0.1);
    float r2_2 = (float)(0.2 * 0.2);
    float r2_3 = (float)(0.4 * 0.4);
    float r2_4 = (float)(0.8 * 0.8);

    // dynamic smem: max(sa: 64*PA + COmax*20 floats, fps tail: S*16 bytes)
    const int SM1 = 16384;                      // sa1 needs 14336; fps2 tail needs 16384
    const int SM2 = (64 * 68 + 128 * 20) * 4;   // 27648 (fps3 tail: 4096)
    const int SM3 = (64 * 132 + 256 * 20) * 4;  // 54272 (fps4 tail: 1024)
    const int SM4 = (64 * 260 + 512 * 20) * 4;  // 107520
    const int SMF1 = NPTS0 * 16;                // 65536

    cudaFuncSetAttribute(k_fps<4096, 1024, 16>,
                         cudaFuncAttributeMaxDynamicSharedMemorySize, SMF1);
    cudaFuncSetAttribute(k_sa<1024, 256, 64, 64, 64, 128, 68, 68, 8, 64>,
                         cudaFuncAttributeMaxDynamicSharedMemorySize, SM2);
    cudaFuncSetAttribute(k_sa<256, 64, 128, 128, 128, 256, 132, 132, 8, 16>,
                         cudaFuncAttributeMaxDynamicSharedMemorySize, SM3);
    cudaFuncSetAttribute(k_sa<64, 16, 256, 256, 256, 512, 260, 260, 2, 0>,
                         cudaFuncAttributeMaxDynamicSharedMemorySize, SM4);

    // stage 0: transpose + output 1
    k_transpose<<<(NBATCH * NPTS0 + 255) / 256, 256>>>(xin, out + O1);

    // fps1 (standalone; nothing to overlap with)
    k_fps<4096, 1024, 16><<<NBATCH, 512, SMF1>>>(p_xyz0, p_nx1, out + O2);

    // layer 1 SA (+ embedded fps2 -> nx2, out O3)
    k_sa<4096, 1024, 9, 32, 32, 64, 12, 36, 8, 256><<<NBATCH * 1024 + NBATCH, 256, SM1>>>(
        p_xyz0, p_pts0, p_nx1, w1a, b1a, w1b, b1b, w1c, b1c,
        p_f1, out + O6, r2_1, p_nx2, out + O3);

    // layer 2 SA (+ embedded fps3 -> nx3, out O4)
    k_sa<1024, 256, 64, 64, 64, 128, 68, 68, 8, 64><<<NBATCH * 256 + NBATCH, 256, SM2>>>(
        p_nx1, p_f1, p_nx2, w2a, b2a, w2b, b2b, w2c, b2c,
        p_f2, out + O7, r2_2, p_nx3, out + O4);

    // layer 3 SA (+ embedded fps4 -> nx4, out O5)
    k_sa<256, 64, 128, 128, 128, 256, 132, 132, 8, 16><<<NBATCH * 64 + NBATCH, 256, SM3>>>(
        p_nx2, p_f2, p_nx3, w3a, b3a, w3b, b3b, w3c, b3c,
        p_f3, out + O8, r2_3, p_nx4, out + O5);

    // layer 4 SA (no tail)
    k_sa<64, 16, 256, 256, 256, 512, 260, 260, 2, 0><<<NBATCH * 16, 256, SM4>>>(
        p_nx3, p_f3, p_nx4, w4a, b4a, w4b, b4b, w4c, b4c,
        p_f4, out + O9, r2_4, nullptr, nullptr);
}